// round 2
// baseline (speedup 1.0000x reference)
#include <cuda_runtime.h>

// preds [B=8, N=16, C=4, H=128, W=256] f32, gt [8,4,128,256] f32, out scalar f32
#define CHW     131072              // C*H*W
#define NCHW    (16 * CHW)
#define NPIX    1048576             // B*C*H*W
#define NTHR    256
#define NBLK    2048                // NBLK*NTHR*2 == NPIX (2 pixels per thread)

__device__ float        g_partials[NBLK];
__device__ unsigned int g_done = 0;

__device__ __forceinline__ void cas2(float2 &a, float2 &b) {
    float2 lo, hi;
    lo.x = fminf(a.x, b.x); hi.x = fmaxf(a.x, b.x);
    lo.y = fminf(a.y, b.y); hi.y = fmaxf(a.y, b.y);
    a = lo; b = hi;
}

__global__ __launch_bounds__(NTHR) void crps_fused(const float* __restrict__ preds,
                                                   const float* __restrict__ gt,
                                                   float* __restrict__ out) {
    const int t    = blockIdx.x * NTHR + threadIdx.x;   // 0 .. 524287
    const int b    = t >> 16;                           // t / (CHW/2)
    const int off2 = t & 65535;                         // float2 index within [C,H,W]

    const float2* pb = reinterpret_cast<const float2*>(preds) + b * (NCHW / 2) + off2;
    const float2  g  = reinterpret_cast<const float2*>(gt)[b * (CHW / 2) + off2];

    // Front-batched ensemble loads: 16 independent LDG.64 (high MLP)
    float2 v[16];
    #pragma unroll
    for (int n = 0; n < 16; n++) v[n] = pb[n * (CHW / 2)];

    // term1: sum over ensemble of |p - g|  (fma pipe)
    float2 t1 = make_float2(0.f, 0.f);
    #pragma unroll
    for (int n = 0; n < 16; n++) {
        t1.x += fabsf(v[n].x - g.x);
        t1.y += fabsf(v[n].y - g.y);
    }

    // Green's 16-input 60-comparator sorting network, component-wise (alu pipe)
    cas2(v[0],v[1]);  cas2(v[2],v[3]);  cas2(v[4],v[5]);  cas2(v[6],v[7]);
    cas2(v[8],v[9]);  cas2(v[10],v[11]);cas2(v[12],v[13]);cas2(v[14],v[15]);
    cas2(v[0],v[2]);  cas2(v[4],v[6]);  cas2(v[8],v[10]); cas2(v[12],v[14]);
    cas2(v[1],v[3]);  cas2(v[5],v[7]);  cas2(v[9],v[11]); cas2(v[13],v[15]);
    cas2(v[0],v[4]);  cas2(v[8],v[12]); cas2(v[1],v[5]);  cas2(v[9],v[13]);
    cas2(v[2],v[6]);  cas2(v[10],v[14]);cas2(v[3],v[7]);  cas2(v[11],v[15]);
    cas2(v[0],v[8]);  cas2(v[1],v[9]);  cas2(v[2],v[10]); cas2(v[3],v[11]);
    cas2(v[4],v[12]); cas2(v[5],v[13]); cas2(v[6],v[14]); cas2(v[7],v[15]);
    cas2(v[5],v[10]); cas2(v[6],v[9]);  cas2(v[3],v[12]); cas2(v[13],v[14]);
    cas2(v[7],v[11]); cas2(v[1],v[2]);  cas2(v[4],v[8]);
    cas2(v[1],v[4]);  cas2(v[7],v[13]); cas2(v[2],v[8]);  cas2(v[11],v[14]);
    cas2(v[5],v[6]);  cas2(v[9],v[10]);
    cas2(v[2],v[4]);  cas2(v[11],v[13]);cas2(v[3],v[8]);  cas2(v[7],v[12]);
    cas2(v[6],v[8]);  cas2(v[10],v[12]);cas2(v[3],v[5]);  cas2(v[7],v[9]);
    cas2(v[3],v[4]);  cas2(v[5],v[6]);  cas2(v[7],v[8]);  cas2(v[9],v[10]);
    cas2(v[11],v[12]);
    cas2(v[6],v[7]);  cas2(v[8],v[9]);

    // term2 from sorted values: sum_{i<j}(x_j - x_i) = sum_k (2k-15) x_k
    float2 t2 = make_float2(0.f, 0.f);
    #pragma unroll
    for (int k = 0; k < 16; k++) {
        const float w = (float)(2 * k - 15);
        t2.x = fmaf(w, v[k].x, t2.x);
        t2.y = fmaf(w, v[k].y, t2.y);
    }

    const float c1 = 1.0f / (16.0f * (float)NPIX);
    const float c2 = 1.0f / (240.0f * (float)NPIX);    // 2 * sum_{i<j} / (2N(N-1))
    float val = (t1.x + t1.y) * c1 - (t2.x + t2.y) * c2;

    // Deterministic block reduction
    #pragma unroll
    for (int o = 16; o > 0; o >>= 1) val += __shfl_down_sync(0xffffffffu, val, o);
    __shared__ float s[NTHR / 32];
    if ((threadIdx.x & 31) == 0) s[threadIdx.x >> 5] = val;
    __syncthreads();
    if (threadIdx.x < (NTHR / 32)) {
        float x = s[threadIdx.x];
        #pragma unroll
        for (int o = (NTHR / 64); o > 0; o >>= 1) x += __shfl_down_sync(0xffu, x, o);
        if (threadIdx.x == 0) g_partials[blockIdx.x] = x;
    }

    // Last-block-done final reduction (deterministic order; atomic only elects)
    __shared__ bool s_last;
    __threadfence();
    if (threadIdx.x == 0) {
        unsigned int r = atomicAdd(&g_done, 1u);
        s_last = (r == (unsigned)(NBLK - 1));
    }
    __syncthreads();
    if (s_last) {
        const int tid = threadIdx.x;
        float acc = 0.f;
        #pragma unroll
        for (int i = 0; i < NBLK / NTHR; i++)          // 8 reads, fixed order
            acc += __ldcg(&g_partials[tid + i * NTHR]);
        #pragma unroll
        for (int o = 16; o > 0; o >>= 1) acc += __shfl_down_sync(0xffffffffu, acc, o);
        __shared__ float s2[NTHR / 32];
        if ((tid & 31) == 0) s2[tid >> 5] = acc;
        __syncthreads();
        if (tid < (NTHR / 32)) {
            float x = s2[tid];
            #pragma unroll
            for (int o = (NTHR / 64); o > 0; o >>= 1) x += __shfl_down_sync(0xffu, x, o);
            if (tid == 0) {
                out[0] = x;
                g_done = 0;                            // reset for next graph replay
            }
        }
    }
}

extern "C" void kernel_launch(void* const* d_in, const int* in_sizes, int n_in,
                              void* d_out, int out_size) {
    const float* preds = (const float*)d_in[0];  // [8,16,4,128,256]
    const float* gt    = (const float*)d_in[1];  // [8,4,128,256]
    float* out = (float*)d_out;                  // scalar f32
    (void)in_sizes; (void)n_in; (void)out_size;
    crps_fused<<<NBLK, NTHR>>>(preds, gt, out);
}

// round 3
// speedup vs baseline: 1.0019x; 1.0019x over previous
#include <cuda_runtime.h>

// preds [B=8, N=16, C=4, H=128, W=256] f32, gt [8,4,128,256] f32, out scalar f32
#define CHW     131072              // C*H*W
#define NCHW    (16 * CHW)
#define NPIX    1048576             // B*C*H*W
#define NTHR    128
#define NBLK    2048                // NBLK*NTHR*4 == NPIX (4 pixels per thread)

__device__ float        g_partials[NBLK];
__device__ unsigned int g_done = 0;

__device__ __forceinline__ void cas4(float4 &a, float4 &b) {
    float4 lo, hi;
    lo.x = fminf(a.x, b.x); hi.x = fmaxf(a.x, b.x);
    lo.y = fminf(a.y, b.y); hi.y = fmaxf(a.y, b.y);
    lo.z = fminf(a.z, b.z); hi.z = fmaxf(a.z, b.z);
    lo.w = fminf(a.w, b.w); hi.w = fmaxf(a.w, b.w);
    a = lo; b = hi;
}

__global__ __launch_bounds__(NTHR) void crps_fused(const float* __restrict__ preds,
                                                   const float* __restrict__ gt,
                                                   float* __restrict__ out) {
    const int t    = blockIdx.x * NTHR + threadIdx.x;   // 0 .. 262143
    const int b    = t >> 15;                           // t / (CHW/4)
    const int off4 = t & 32767;                         // float4 index within [C,H,W]

    // gt load first: earliest consumer (term1), retire its scoreboard first
    const float4  g  = reinterpret_cast<const float4*>(gt)[b * (CHW / 4) + off4];
    const float4* pb = reinterpret_cast<const float4*>(preds) + b * (NCHW / 4) + off4;

    // Front-batched ensemble loads: 16 independent LDG.128 (high MLP)
    float4 v[16];
    #pragma unroll
    for (int n = 0; n < 16; n++) v[n] = pb[n * (CHW / 4)];

    // term1: sum over ensemble of |p - g|  (fma pipe, abs folds as src modifier)
    float4 t1 = make_float4(0.f, 0.f, 0.f, 0.f);
    #pragma unroll
    for (int n = 0; n < 16; n++) {
        t1.x += fabsf(v[n].x - g.x);
        t1.y += fabsf(v[n].y - g.y);
        t1.z += fabsf(v[n].z - g.z);
        t1.w += fabsf(v[n].w - g.w);
    }

    // Green's 16-input 60-comparator sorting network, component-wise
    // (4 pixels sorted simultaneously -> 4-wide ILP per comparator level)
    cas4(v[0],v[1]);  cas4(v[2],v[3]);  cas4(v[4],v[5]);  cas4(v[6],v[7]);
    cas4(v[8],v[9]);  cas4(v[10],v[11]);cas4(v[12],v[13]);cas4(v[14],v[15]);
    cas4(v[0],v[2]);  cas4(v[4],v[6]);  cas4(v[8],v[10]); cas4(v[12],v[14]);
    cas4(v[1],v[3]);  cas4(v[5],v[7]);  cas4(v[9],v[11]); cas4(v[13],v[15]);
    cas4(v[0],v[4]);  cas4(v[8],v[12]); cas4(v[1],v[5]);  cas4(v[9],v[13]);
    cas4(v[2],v[6]);  cas4(v[10],v[14]);cas4(v[3],v[7]);  cas4(v[11],v[15]);
    cas4(v[0],v[8]);  cas4(v[1],v[9]);  cas4(v[2],v[10]); cas4(v[3],v[11]);
    cas4(v[4],v[12]); cas4(v[5],v[13]); cas4(v[6],v[14]); cas4(v[7],v[15]);
    cas4(v[5],v[10]); cas4(v[6],v[9]);  cas4(v[3],v[12]); cas4(v[13],v[14]);
    cas4(v[7],v[11]); cas4(v[1],v[2]);  cas4(v[4],v[8]);
    cas4(v[1],v[4]);  cas4(v[7],v[13]); cas4(v[2],v[8]);  cas4(v[11],v[14]);
    cas4(v[5],v[6]);  cas4(v[9],v[10]);
    cas4(v[2],v[4]);  cas4(v[11],v[13]);cas4(v[3],v[8]);  cas4(v[7],v[12]);
    cas4(v[6],v[8]);  cas4(v[10],v[12]);cas4(v[3],v[5]);  cas4(v[7],v[9]);
    cas4(v[3],v[4]);  cas4(v[5],v[6]);  cas4(v[7],v[8]);  cas4(v[9],v[10]);
    cas4(v[11],v[12]);
    cas4(v[6],v[7]);  cas4(v[8],v[9]);

    // term2 from sorted values: sum_{i<j}(x_j - x_i) = sum_k (2k-15) x_k
    float4 t2 = make_float4(0.f, 0.f, 0.f, 0.f);
    #pragma unroll
    for (int k = 0; k < 16; k++) {
        const float w = (float)(2 * k - 15);
        t2.x = fmaf(w, v[k].x, t2.x);
        t2.y = fmaf(w, v[k].y, t2.y);
        t2.z = fmaf(w, v[k].z, t2.z);
        t2.w = fmaf(w, v[k].w, t2.w);
    }

    const float c1 = 1.0f / (16.0f * (float)NPIX);
    const float c2 = 1.0f / (240.0f * (float)NPIX);    // 2*sum_{i<j} / (2N(N-1))
    float val = (t1.x + t1.y + t1.z + t1.w) * c1
              - (t2.x + t2.y + t2.z + t2.w) * c2;

    // Deterministic block reduction (128 threads = 4 warps)
    #pragma unroll
    for (int o = 16; o > 0; o >>= 1) val += __shfl_down_sync(0xffffffffu, val, o);
    __shared__ float s[NTHR / 32];
    if ((threadIdx.x & 31) == 0) s[threadIdx.x >> 5] = val;
    __syncthreads();
    if (threadIdx.x < 32) {
        float x = (threadIdx.x < (NTHR / 32)) ? s[threadIdx.x] : 0.f;
        #pragma unroll
        for (int o = 2; o > 0; o >>= 1) x += __shfl_down_sync(0xfu, x, o);
        if (threadIdx.x == 0) g_partials[blockIdx.x] = x;
    }

    // Last-block-done final reduction (deterministic order; atomic only elects)
    __shared__ bool s_last;
    __threadfence();
    if (threadIdx.x == 0) {
        unsigned int r = atomicAdd(&g_done, 1u);
        s_last = (r == (unsigned)(NBLK - 1));
    }
    __syncthreads();
    if (s_last) {
        const int tid = threadIdx.x;
        float acc = 0.f;
        #pragma unroll
        for (int i = 0; i < NBLK / NTHR; i++)          // 16 reads, fixed order
            acc += __ldcg(&g_partials[tid + i * NTHR]);
        #pragma unroll
        for (int o = 16; o > 0; o >>= 1) acc += __shfl_down_sync(0xffffffffu, acc, o);
        __shared__ float s2[NTHR / 32];
        if ((tid & 31) == 0) s2[tid >> 5] = acc;
        __syncthreads();
        if (tid == 0) {
            float x = s2[0] + s2[1] + s2[2] + s2[3];
            out[0] = x;
            g_done = 0;                                // reset for next graph replay
        }
    }
}

extern "C" void kernel_launch(void* const* d_in, const int* in_sizes, int n_in,
                              void* d_out, int out_size) {
    const float* preds = (const float*)d_in[0];  // [8,16,4,128,256]
    const float* gt    = (const float*)d_in[1];  // [8,4,128,256]
    float* out = (float*)d_out;                  // scalar f32
    (void)in_sizes; (void)n_in; (void)out_size;
    crps_fused<<<NBLK, NTHR>>>(preds, gt, out);
}